// round 5
// baseline (speedup 1.0000x reference)
#include <cuda_runtime.h>
#include <cuda_fp16.h>

#define NN 100000
#define EE 1200000
#define IDXM 0x3FFFFFFF
#define M1BIT (1u << 30)
#define M2BIT (1u << 31)

// Scratch (allocation-free contract: static __device__ arrays)
__device__ __half2 g_HN[(size_t)NN * 32];   // LN(feature), 64 cols as 32 half2
__device__ __half2 g_HB[(size_t)NN * 96];   // layer-1 state, 3 windows x 32 half2
__device__ int     g_deg[NN];
__device__ int     g_rowptr[NN + 1];
__device__ int     g_cursor[NN];
__device__ unsigned g_ssrc[EE];             // src index | mask bits 30/31

// ---------------- CSR build ----------------

__global__ void k_zero_deg() {
    int i = blockIdx.x * blockDim.x + threadIdx.x;
    if (i < NN) g_deg[i] = 0;
}

__global__ void k_hist(const int* __restrict__ dst) {
    int e = blockIdx.x * blockDim.x + threadIdx.x;
    if (e < EE) atomicAdd(&g_deg[dst[e]], 1);
}

__global__ void k_scan() {
    __shared__ int part[1024];
    const int CH = (NN + 1023) / 1024;   // 98
    int t = threadIdx.x;
    int base = t * CH;
    int s = 0;
    #pragma unroll 4
    for (int i = 0; i < CH; i++) {
        int idx = base + i;
        if (idx < NN) s += g_deg[idx];
    }
    part[t] = s;
    __syncthreads();
    for (int off = 1; off < 1024; off <<= 1) {
        int v = (t >= off) ? part[t - off] : 0;
        __syncthreads();
        part[t] += v;
        __syncthreads();
    }
    int run = (t == 0) ? 0 : part[t - 1];
    for (int i = 0; i < CH; i++) {
        int idx = base + i;
        if (idx < NN) {
            g_rowptr[idx] = run;
            g_cursor[idx] = run;
            run += g_deg[idx];
        }
    }
    if (t == 1023) g_rowptr[NN] = part[1023];
}

// Scatter + pack the source node's window masks into bits 30/31.
__global__ void k_scatter(const int* __restrict__ src, const int* __restrict__ dst,
                          const int* __restrict__ age) {
    int e = blockIdx.x * blockDim.x + threadIdx.x;
    if (e < EE) {
        int s = src[e];
        int a = __ldg(&age[s]);
        unsigned v = (unsigned)s;
        if (a >= 1) v |= M1BIT;
        if (a >= 2) v |= M2BIT;
        int p = atomicAdd(&g_cursor[dst[e]], 1);
        g_ssrc[p] = v;
    }
}

// ---------------- compute ----------------

__device__ __forceinline__ float warp_sum(float v) {
    #pragma unroll
    for (int o = 16; o > 0; o >>= 1) v += __shfl_xor_sync(0xffffffffu, v, o);
    return v;
}

// lane t owns cols (2t, 2t+1); out viewed as float2 rows of 192.

__global__ void k_ln0(const float* __restrict__ feat, const int* __restrict__ age,
                      float2* __restrict__ out) {
    int n = blockIdx.x * 8 + (threadIdx.x >> 5);   // grid = NN/8 exactly
    int t = threadIdx.x & 31;
    const float2* f = (const float2*)(feat + (size_t)n * 64);
    float2 v = __ldg(&f[t]);
    float s = warp_sum(v.x + v.y);
    float q = warp_sum(v.x * v.x + v.y * v.y);
    float mean = s * (1.0f / 64.0f);
    float var  = q * (1.0f / 64.0f) - mean * mean;
    float r = rsqrtf(var + 1e-5f);
    float ha = (v.x - mean) * r, hb = (v.y - mean) * r;
    int ag = __ldg(&age[n]);
    float m1 = (ag >= 1) ? 1.0f : 0.0f;
    float m2 = (ag >= 2) ? 1.0f : 0.0f;
    g_HN[(size_t)n * 32 + t] = __floats2half2_rn(ha, hb);
    float2* o = out + (size_t)n * 192;
    o[t] = make_float2(ha, hb);
    float c = 1.0f - 0.5f * (m1 + m2);
    o[96 + t] = make_float2(ha * c, hb * c);
}

// Layer 1: gather 64-wide fp16 rows; masks decoded from index bits. Unroll 8.
__global__ void __launch_bounds__(256) k_spmm1(float2* __restrict__ out) {
    int n = blockIdx.x * 8 + (threadIdx.x >> 5);
    int t = threadIdx.x & 31;

    float w0x = 0.f, w0y = 0.f, w1x = 0.f, w1y = 0.f, w2x = 0.f, w2y = 0.f;
    int beg = g_rowptr[n], end = g_rowptr[n + 1];
    int e = beg;
    for (; e + 8 <= end; e += 8) {
        unsigned p[8];
        #pragma unroll
        for (int i = 0; i < 8; i++) p[i] = __ldg(&g_ssrc[e + i]);
        __half2 h[8];
        #pragma unroll
        for (int i = 0; i < 8; i++)
            h[i] = __ldg(&g_HN[(size_t)(p[i] & IDXM) * 32 + t]);
        #pragma unroll
        for (int i = 0; i < 8; i++) {
            float2 f0 = __half22float2(h[i]);
            float m1 = (p[i] & M1BIT) ? 1.0f : 0.0f;
            float m2 = (p[i] & M2BIT) ? 1.0f : 0.0f;
            w0x += f0.x;        w0y += f0.y;
            w1x += f0.x * m1;   w1y += f0.y * m1;
            w2x += f0.x * m2;   w2y += f0.y * m2;
        }
    }
    for (; e < end; e++) {
        unsigned p0 = __ldg(&g_ssrc[e]);
        float2 f0 = __half22float2(__ldg(&g_HN[(size_t)(p0 & IDXM) * 32 + t]));
        float m1 = (p0 & M1BIT) ? 1.0f : 0.0f;
        float m2 = (p0 & M2BIT) ? 1.0f : 0.0f;
        w0x += f0.x;        w0y += f0.y;
        w1x += f0.x * m1;   w1y += f0.y * m1;
        w2x += f0.x * m2;   w2y += f0.y * m2;
    }

    float y0x, y0y, y1x, y1y, y2x, y2y;
    {
        float s = warp_sum(w0x + w0y);
        float q = warp_sum(w0x * w0x + w0y * w0y);
        float mean = s * (1.0f / 64.0f);
        float var  = q * (1.0f / 64.0f) - mean * mean;
        float r = rsqrtf(var + 1e-5f);
        y0x = fmaxf((w0x - mean) * r, 0.f);
        y0y = fmaxf((w0y - mean) * r, 0.f);
    }
    {
        float s = warp_sum(w1x + w1y);
        float q = warp_sum(w1x * w1x + w1y * w1y);
        float mean = s * (1.0f / 64.0f);
        float var  = q * (1.0f / 64.0f) - mean * mean;
        float r = rsqrtf(var + 1e-5f);
        y1x = fmaxf((w1x - mean) * r, 0.f);
        y1y = fmaxf((w1y - mean) * r, 0.f);
    }
    {
        float s = warp_sum(w2x + w2y);
        float q = warp_sum(w2x * w2x + w2y * w2y);
        float mean = s * (1.0f / 64.0f);
        float var  = q * (1.0f / 64.0f) - mean * mean;
        float r = rsqrtf(var + 1e-5f);
        y2x = fmaxf((w2x - mean) * r, 0.f);
        y2y = fmaxf((w2y - mean) * r, 0.f);
    }

    __half2* Ho = g_HB + (size_t)n * 96;
    Ho[t]      = __floats2half2_rn(y0x, y0y);
    Ho[32 + t] = __floats2half2_rn(y1x, y1y);
    Ho[64 + t] = __floats2half2_rn(y2x, y2y);

    float2* o = out + (size_t)n * 192;
    o[32 + t]  = make_float2(y0x, y0y);
    o[128 + t] = make_float2(y0x - 0.5f * (y1x + y2x), y0y - 0.5f * (y1y + y2y));
}

// Layer 2: gather 192-wide fp16 rows. Unroll 8 (24 loads in flight per lane).
__global__ void __launch_bounds__(256) k_spmm2(float2* __restrict__ out) {
    int n = blockIdx.x * 8 + (threadIdx.x >> 5);
    int t = threadIdx.x & 31;

    float w0x = 0.f, w0y = 0.f, w1x = 0.f, w1y = 0.f, w2x = 0.f, w2y = 0.f;
    int beg = g_rowptr[n], end = g_rowptr[n + 1];
    int e = beg;
    for (; e + 8 <= end; e += 8) {
        const __half2* r[8];
        #pragma unroll
        for (int i = 0; i < 8; i++) {
            unsigned p = __ldg(&g_ssrc[e + i]);
            r[i] = g_HB + (size_t)(p & IDXM) * 96;
        }
        __half2 a[8], b[8], c[8];
        #pragma unroll
        for (int i = 0; i < 8; i++) a[i] = __ldg(&r[i][t]);
        #pragma unroll
        for (int i = 0; i < 8; i++) b[i] = __ldg(&r[i][32 + t]);
        #pragma unroll
        for (int i = 0; i < 8; i++) c[i] = __ldg(&r[i][64 + t]);
        #pragma unroll
        for (int i = 0; i < 8; i++) {
            float2 fa = __half22float2(a[i]);
            float2 fb = __half22float2(b[i]);
            float2 fc = __half22float2(c[i]);
            w0x += fa.x; w0y += fa.y;
            w1x += fb.x; w1y += fb.y;
            w2x += fc.x; w2y += fc.y;
        }
    }
    for (; e < end; e++) {
        unsigned p = __ldg(&g_ssrc[e]);
        const __half2* r0 = g_HB + (size_t)(p & IDXM) * 96;
        float2 fa = __half22float2(__ldg(&r0[t]));
        float2 fb = __half22float2(__ldg(&r0[32 + t]));
        float2 fc = __half22float2(__ldg(&r0[64 + t]));
        w0x += fa.x; w0y += fa.y;
        w1x += fb.x; w1y += fb.y;
        w2x += fc.x; w2y += fc.y;
    }

    float y0x, y0y, y1x, y1y, y2x, y2y;
    {
        float s = warp_sum(w0x + w0y);
        float q = warp_sum(w0x * w0x + w0y * w0y);
        float mean = s * (1.0f / 64.0f);
        float var  = q * (1.0f / 64.0f) - mean * mean;
        float r = rsqrtf(var + 1e-5f);
        y0x = fmaxf((w0x - mean) * r, 0.f);
        y0y = fmaxf((w0y - mean) * r, 0.f);
    }
    {
        float s = warp_sum(w1x + w1y);
        float q = warp_sum(w1x * w1x + w1y * w1y);
        float mean = s * (1.0f / 64.0f);
        float var  = q * (1.0f / 64.0f) - mean * mean;
        float r = rsqrtf(var + 1e-5f);
        y1x = fmaxf((w1x - mean) * r, 0.f);
        y1y = fmaxf((w1y - mean) * r, 0.f);
    }
    {
        float s = warp_sum(w2x + w2y);
        float q = warp_sum(w2x * w2x + w2y * w2y);
        float mean = s * (1.0f / 64.0f);
        float var  = q * (1.0f / 64.0f) - mean * mean;
        float r = rsqrtf(var + 1e-5f);
        y2x = fmaxf((w2x - mean) * r, 0.f);
        y2y = fmaxf((w2y - mean) * r, 0.f);
    }

    float2* o = out + (size_t)n * 192;
    o[64 + t]  = make_float2(y0x, y0y);
    o[160 + t] = make_float2(y0x - 0.5f * (y1x + y2x), y0y - 0.5f * (y1y + y2y));
}

// ---------------- launch ----------------

extern "C" void kernel_launch(void* const* d_in, const int* in_sizes, int n_in,
                              void* d_out, int out_size) {
    const float* feature = (const float*)d_in[0];
    const int*   age     = (const int*)d_in[1];
    const int*   src     = (const int*)d_in[2];
    const int*   dst     = (const int*)d_in[3];
    float2* out = (float2*)d_out;

    (void)in_sizes; (void)n_in; (void)out_size;

    static cudaStream_t s2 = nullptr;
    static cudaEvent_t evFork = nullptr, evJoin = nullptr;
    if (!s2) {
        cudaStreamCreateWithFlags(&s2, cudaStreamNonBlocking);
        cudaEventCreateWithFlags(&evFork, cudaEventDisableTiming);
        cudaEventCreateWithFlags(&evJoin, cudaEventDisableTiming);
    }

    // Fork: ln0 (dense LN) overlaps the CSR-build chain.
    cudaEventRecord(evFork, 0);
    cudaStreamWaitEvent(s2, evFork, 0);
    k_ln0<<<NN / 8, 256, 0, s2>>>(feature, age, out);
    cudaEventRecord(evJoin, s2);

    // CSR build (by destination) on the main stream.
    k_zero_deg<<<(NN + 255) / 256, 256>>>();
    k_hist<<<(EE + 255) / 256, 256>>>(dst);
    k_scan<<<1, 1024>>>();
    k_scatter<<<(EE + 255) / 256, 256>>>(src, dst, age);

    // Join, then the two SpMM layers.
    cudaStreamWaitEvent(0, evJoin, 0);
    k_spmm1<<<NN / 8, 256>>>(out);
    k_spmm2<<<NN / 8, 256>>>(out);
}

// round 6
// speedup vs baseline: 2.0085x; 2.0085x over previous
#include <cuda_runtime.h>
#include <cuda_fp16.h>

#define NN 100000
#define EE 1200000
#define IDXM 0x3FFFFFFF
#define M1BIT (1u << 30)
#define M2BIT (1u << 31)
#define SCAN_B 512
#define NBLK ((NN + SCAN_B - 1) / SCAN_B)   // 196

// Scratch (allocation-free contract: static __device__ arrays)
__device__ __half2 g_HN[(size_t)NN * 32];   // LN(feature), 64 cols as 32 half2
__device__ __half2 g_HB[(size_t)NN * 96];   // layer-1 state, 3 windows x 32 half2
__device__ int     g_deg[NN];
__device__ int     g_rowptr[NN + 1];
__device__ int     g_cursor[NN];
__device__ int     g_bsum[NBLK];
__device__ unsigned g_ssrc[EE];             // src index | mask bits 30/31

// ---------------- CSR build ----------------

__global__ void k_zero_deg() {
    int i = blockIdx.x * blockDim.x + threadIdx.x;
    if (i < NN) g_deg[i] = 0;
}

__global__ void k_hist(const int* __restrict__ dst) {
    int e = blockIdx.x * blockDim.x + threadIdx.x;
    if (e < EE) atomicAdd(&g_deg[dst[e]], 1);
}

// Phase 1: per-block inclusive scan (coalesced), local-exclusive to rowptr, totals to bsum.
__global__ void k_scan1() {
    __shared__ int sh[SCAN_B];
    int i = blockIdx.x * SCAN_B + threadIdx.x;
    int v = (i < NN) ? g_deg[i] : 0;
    sh[threadIdx.x] = v;
    __syncthreads();
    #pragma unroll
    for (int off = 1; off < SCAN_B; off <<= 1) {
        int x = (threadIdx.x >= off) ? sh[threadIdx.x - off] : 0;
        __syncthreads();
        sh[threadIdx.x] += x;
        __syncthreads();
    }
    if (i < NN) g_rowptr[i] = sh[threadIdx.x] - v;   // block-local exclusive
    if (threadIdx.x == SCAN_B - 1) g_bsum[blockIdx.x] = sh[threadIdx.x];
}

// Phase 2: exclusive scan of the 196 block sums; also writes rowptr[NN].
__global__ void k_scan2() {
    __shared__ int sh[256];
    int t = threadIdx.x;
    int v = (t < NBLK) ? g_bsum[t] : 0;
    sh[t] = v;
    __syncthreads();
    #pragma unroll
    for (int off = 1; off < 256; off <<= 1) {
        int x = (t >= off) ? sh[t - off] : 0;
        __syncthreads();
        sh[t] += x;
        __syncthreads();
    }
    if (t < NBLK) g_bsum[t] = sh[t] - v;             // exclusive block offset
    if (t == 255) g_rowptr[NN] = sh[255];
}

// Phase 3: add block offsets; mirror into cursor.
__global__ void k_scan3() {
    int i = blockIdx.x * blockDim.x + threadIdx.x;
    if (i < NN) {
        int r = g_rowptr[i] + g_bsum[i / SCAN_B];
        g_rowptr[i] = r;
        g_cursor[i] = r;
    }
}

// Scatter + pack the source node's window masks into bits 30/31.
__global__ void k_scatter(const int* __restrict__ src, const int* __restrict__ dst,
                          const int* __restrict__ age) {
    int e = blockIdx.x * blockDim.x + threadIdx.x;
    if (e < EE) {
        int s = src[e];
        int a = __ldg(&age[s]);
        unsigned v = (unsigned)s;
        if (a >= 1) v |= M1BIT;
        if (a >= 2) v |= M2BIT;
        int p = atomicAdd(&g_cursor[dst[e]], 1);
        g_ssrc[p] = v;
    }
}

// ---------------- compute ----------------

__device__ __forceinline__ float warp_sum(float v) {
    #pragma unroll
    for (int o = 16; o > 0; o >>= 1) v += __shfl_xor_sync(0xffffffffu, v, o);
    return v;
}

// lane t owns cols (2t, 2t+1); out viewed as float2 rows of 192.

__global__ void k_ln0(const float* __restrict__ feat, const int* __restrict__ age,
                      float2* __restrict__ out) {
    int n = blockIdx.x * 8 + (threadIdx.x >> 5);   // grid = NN/8 exactly
    int t = threadIdx.x & 31;
    const float2* f = (const float2*)(feat + (size_t)n * 64);
    float2 v = __ldg(&f[t]);
    float s = warp_sum(v.x + v.y);
    float q = warp_sum(v.x * v.x + v.y * v.y);
    float mean = s * (1.0f / 64.0f);
    float var  = q * (1.0f / 64.0f) - mean * mean;
    float r = rsqrtf(var + 1e-5f);
    float ha = (v.x - mean) * r, hb = (v.y - mean) * r;
    int ag = __ldg(&age[n]);
    float m1 = (ag >= 1) ? 1.0f : 0.0f;
    float m2 = (ag >= 2) ? 1.0f : 0.0f;
    g_HN[(size_t)n * 32 + t] = __floats2half2_rn(ha, hb);
    float2* o = out + (size_t)n * 192;
    o[t] = make_float2(ha, hb);
    float c = 1.0f - 0.5f * (m1 + m2);
    o[96 + t] = make_float2(ha * c, hb * c);
}

// Layer 1: gather 64-wide fp16 rows; masks decoded from index bits. Unroll 8.
__global__ void __launch_bounds__(256) k_spmm1(float2* __restrict__ out) {
    int n = blockIdx.x * 8 + (threadIdx.x >> 5);
    int t = threadIdx.x & 31;

    float w0x = 0.f, w0y = 0.f, w1x = 0.f, w1y = 0.f, w2x = 0.f, w2y = 0.f;
    int beg = g_rowptr[n], end = g_rowptr[n + 1];
    int e = beg;
    for (; e + 8 <= end; e += 8) {
        unsigned p[8];
        #pragma unroll
        for (int i = 0; i < 8; i++) p[i] = __ldg(&g_ssrc[e + i]);
        __half2 h[8];
        #pragma unroll
        for (int i = 0; i < 8; i++)
            h[i] = __ldg(&g_HN[(size_t)(p[i] & IDXM) * 32 + t]);
        #pragma unroll
        for (int i = 0; i < 8; i++) {
            float2 f0 = __half22float2(h[i]);
            float m1 = (p[i] & M1BIT) ? 1.0f : 0.0f;
            float m2 = (p[i] & M2BIT) ? 1.0f : 0.0f;
            w0x += f0.x;        w0y += f0.y;
            w1x += f0.x * m1;   w1y += f0.y * m1;
            w2x += f0.x * m2;   w2y += f0.y * m2;
        }
    }
    for (; e < end; e++) {
        unsigned p0 = __ldg(&g_ssrc[e]);
        float2 f0 = __half22float2(__ldg(&g_HN[(size_t)(p0 & IDXM) * 32 + t]));
        float m1 = (p0 & M1BIT) ? 1.0f : 0.0f;
        float m2 = (p0 & M2BIT) ? 1.0f : 0.0f;
        w0x += f0.x;        w0y += f0.y;
        w1x += f0.x * m1;   w1y += f0.y * m1;
        w2x += f0.x * m2;   w2y += f0.y * m2;
    }

    float y0x, y0y, y1x, y1y, y2x, y2y;
    {
        float s = warp_sum(w0x + w0y);
        float q = warp_sum(w0x * w0x + w0y * w0y);
        float mean = s * (1.0f / 64.0f);
        float var  = q * (1.0f / 64.0f) - mean * mean;
        float r = rsqrtf(var + 1e-5f);
        y0x = fmaxf((w0x - mean) * r, 0.f);
        y0y = fmaxf((w0y - mean) * r, 0.f);
    }
    {
        float s = warp_sum(w1x + w1y);
        float q = warp_sum(w1x * w1x + w1y * w1y);
        float mean = s * (1.0f / 64.0f);
        float var  = q * (1.0f / 64.0f) - mean * mean;
        float r = rsqrtf(var + 1e-5f);
        y1x = fmaxf((w1x - mean) * r, 0.f);
        y1y = fmaxf((w1y - mean) * r, 0.f);
    }
    {
        float s = warp_sum(w2x + w2y);
        float q = warp_sum(w2x * w2x + w2y * w2y);
        float mean = s * (1.0f / 64.0f);
        float var  = q * (1.0f / 64.0f) - mean * mean;
        float r = rsqrtf(var + 1e-5f);
        y2x = fmaxf((w2x - mean) * r, 0.f);
        y2y = fmaxf((w2y - mean) * r, 0.f);
    }

    __half2* Ho = g_HB + (size_t)n * 96;
    Ho[t]      = __floats2half2_rn(y0x, y0y);
    Ho[32 + t] = __floats2half2_rn(y1x, y1y);
    Ho[64 + t] = __floats2half2_rn(y2x, y2y);

    float2* o = out + (size_t)n * 192;
    o[32 + t]  = make_float2(y0x, y0y);
    o[128 + t] = make_float2(y0x - 0.5f * (y1x + y2x), y0y - 0.5f * (y1y + y2y));
}

// Layer 2: gather 192-wide fp16 rows. Unroll 8 (24 loads in flight per lane).
__global__ void __launch_bounds__(256) k_spmm2(float2* __restrict__ out) {
    int n = blockIdx.x * 8 + (threadIdx.x >> 5);
    int t = threadIdx.x & 31;

    float w0x = 0.f, w0y = 0.f, w1x = 0.f, w1y = 0.f, w2x = 0.f, w2y = 0.f;
    int beg = g_rowptr[n], end = g_rowptr[n + 1];
    int e = beg;
    for (; e + 8 <= end; e += 8) {
        const __half2* r[8];
        #pragma unroll
        for (int i = 0; i < 8; i++) {
            unsigned p = __ldg(&g_ssrc[e + i]);
            r[i] = g_HB + (size_t)(p & IDXM) * 96;
        }
        __half2 a[8], b[8], c[8];
        #pragma unroll
        for (int i = 0; i < 8; i++) a[i] = __ldg(&r[i][t]);
        #pragma unroll
        for (int i = 0; i < 8; i++) b[i] = __ldg(&r[i][32 + t]);
        #pragma unroll
        for (int i = 0; i < 8; i++) c[i] = __ldg(&r[i][64 + t]);
        #pragma unroll
        for (int i = 0; i < 8; i++) {
            float2 fa = __half22float2(a[i]);
            float2 fb = __half22float2(b[i]);
            float2 fc = __half22float2(c[i]);
            w0x += fa.x; w0y += fa.y;
            w1x += fb.x; w1y += fb.y;
            w2x += fc.x; w2y += fc.y;
        }
    }
    for (; e < end; e++) {
        unsigned p = __ldg(&g_ssrc[e]);
        const __half2* r0 = g_HB + (size_t)(p & IDXM) * 96;
        float2 fa = __half22float2(__ldg(&r0[t]));
        float2 fb = __half22float2(__ldg(&r0[32 + t]));
        float2 fc = __half22float2(__ldg(&r0[64 + t]));
        w0x += fa.x; w0y += fa.y;
        w1x += fb.x; w1y += fb.y;
        w2x += fc.x; w2y += fc.y;
    }

    float y0x, y0y, y1x, y1y, y2x, y2y;
    {
        float s = warp_sum(w0x + w0y);
        float q = warp_sum(w0x * w0x + w0y * w0y);
        float mean = s * (1.0f / 64.0f);
        float var  = q * (1.0f / 64.0f) - mean * mean;
        float r = rsqrtf(var + 1e-5f);
        y0x = fmaxf((w0x - mean) * r, 0.f);
        y0y = fmaxf((w0y - mean) * r, 0.f);
    }
    {
        float s = warp_sum(w1x + w1y);
        float q = warp_sum(w1x * w1x + w1y * w1y);
        float mean = s * (1.0f / 64.0f);
        float var  = q * (1.0f / 64.0f) - mean * mean;
        float r = rsqrtf(var + 1e-5f);
        y1x = fmaxf((w1x - mean) * r, 0.f);
        y1y = fmaxf((w1y - mean) * r, 0.f);
    }
    {
        float s = warp_sum(w2x + w2y);
        float q = warp_sum(w2x * w2x + w2y * w2y);
        float mean = s * (1.0f / 64.0f);
        float var  = q * (1.0f / 64.0f) - mean * mean;
        float r = rsqrtf(var + 1e-5f);
        y2x = fmaxf((w2x - mean) * r, 0.f);
        y2y = fmaxf((w2y - mean) * r, 0.f);
    }

    float2* o = out + (size_t)n * 192;
    o[64 + t]  = make_float2(y0x, y0y);
    o[160 + t] = make_float2(y0x - 0.5f * (y1x + y2x), y0y - 0.5f * (y1y + y2y));
}

// ---------------- launch ----------------

extern "C" void kernel_launch(void* const* d_in, const int* in_sizes, int n_in,
                              void* d_out, int out_size) {
    const float* feature = (const float*)d_in[0];
    const int*   age     = (const int*)d_in[1];
    const int*   src     = (const int*)d_in[2];
    const int*   dst     = (const int*)d_in[3];
    float2* out = (float2*)d_out;

    (void)in_sizes; (void)n_in; (void)out_size;

    static cudaStream_t s2 = nullptr;
    static cudaEvent_t evFork = nullptr, evJoin = nullptr;
    if (!s2) {
        cudaStreamCreateWithFlags(&s2, cudaStreamNonBlocking);
        cudaEventCreateWithFlags(&evFork, cudaEventDisableTiming);
        cudaEventCreateWithFlags(&evJoin, cudaEventDisableTiming);
    }

    // Fork: ln0 (dense LN) overlaps the CSR-build chain.
    cudaEventRecord(evFork, 0);
    cudaStreamWaitEvent(s2, evFork, 0);
    k_ln0<<<NN / 8, 256, 0, s2>>>(feature, age, out);
    cudaEventRecord(evJoin, s2);

    // CSR build (by destination) on the main stream.
    k_zero_deg<<<(NN + 255) / 256, 256>>>();
    k_hist<<<(EE + 255) / 256, 256>>>(dst);
    k_scan1<<<NBLK, SCAN_B>>>();
    k_scan2<<<1, 256>>>();
    k_scan3<<<(NN + 255) / 256, 256>>>();
    k_scatter<<<(EE + 255) / 256, 256>>>(src, dst, age);

    // Join, then the two SpMM layers.
    cudaStreamWaitEvent(0, evJoin, 0);
    k_spmm1<<<NN / 8, 256>>>(out);
    k_spmm2<<<NN / 8, 256>>>(out);
}